// round 1
// baseline (speedup 1.0000x reference)
#include <cuda_runtime.h>
#include <stdint.h>

#define B_ 16
#define L_ 576
#define H_ 12
#define D_ 64
#define M_ 8
#define RATIO 0.35355339059327373f   // 1/sqrt(8)
#define EPS 1e-3f

// Scratch (device globals; no dynamic allocation allowed)
__device__ float g_qp[B_*H_*L_*M_];   // q' in [B,H,L,M]
__device__ float g_kp[B_*H_*L_*M_];   // k' in [B,H,L,M]
__device__ float g_s [H_*L_];         // column sums of mask
__device__ float g_ks[B_*H_*M_];      // ks_sum

// ---------------------------------------------------------------------------
// Feature kernel: qp/kp = relu(ratio * x @ proj^T) + eps, written as [B,H,L,M]
// grid.y == 0 -> query, grid.y == 1 -> key
// ---------------------------------------------------------------------------
__global__ __launch_bounds__(128) void feat_kernel(const float* __restrict__ q,
                                                   const float* __restrict__ kk,
                                                   const float* __restrict__ proj)
{
    __shared__ float pr[M_*D_];
    int tid = threadIdx.x;
    for (int i = tid; i < M_*D_; i += 128) pr[i] = proj[i];
    __syncthreads();

    int rid = blockIdx.x * 128 + tid;          // row over (b,l,h)
    if (rid >= B_*L_*H_) return;

    const float* src = (blockIdx.y == 0 ? q : kk) + (size_t)rid * D_;
    float*       dst = (blockIdx.y == 0 ? g_qp : g_kp);

    float o[M_];
#pragma unroll
    for (int m = 0; m < M_; m++) o[m] = 0.f;

#pragma unroll
    for (int i = 0; i < D_/4; i++) {
        float4 x4 = ((const float4*)src)[i];
#pragma unroll
        for (int m = 0; m < M_; m++) {
            o[m] += x4.x * pr[m*D_ + 4*i + 0]
                  + x4.y * pr[m*D_ + 4*i + 1]
                  + x4.z * pr[m*D_ + 4*i + 2]
                  + x4.w * pr[m*D_ + 4*i + 3];
        }
    }

    int b   = rid / (L_*H_);
    int rem = rid - b*(L_*H_);
    int l   = rem / H_;
    int h   = rem - l*H_;
    size_t orow = ((size_t)(b*H_ + h)*L_ + l) * M_;

    float4 r0, r1;
    r0.x = fmaxf(o[0]*RATIO, 0.f) + EPS;
    r0.y = fmaxf(o[1]*RATIO, 0.f) + EPS;
    r0.z = fmaxf(o[2]*RATIO, 0.f) + EPS;
    r0.w = fmaxf(o[3]*RATIO, 0.f) + EPS;
    r1.x = fmaxf(o[4]*RATIO, 0.f) + EPS;
    r1.y = fmaxf(o[5]*RATIO, 0.f) + EPS;
    r1.z = fmaxf(o[6]*RATIO, 0.f) + EPS;
    r1.w = fmaxf(o[7]*RATIO, 0.f) + EPS;
    ((float4*)(dst + orow))[0] = r0;
    ((float4*)(dst + orow))[1] = r1;
}

// ---------------------------------------------------------------------------
// Column sums of mask: s[h,j] = sum_i mask[h,i,j]
// ---------------------------------------------------------------------------
__global__ __launch_bounds__(256) void colsum_kernel(const float* __restrict__ mask)
{
    int idx = blockIdx.x * 256 + threadIdx.x;
    if (idx >= H_*L_) return;
    int h = idx / L_;
    int j = idx - h*L_;
    const float* p = mask + (size_t)h*L_*L_ + j;
    float acc = 0.f;
    for (int i = 0; i < L_; i++) acc += p[(size_t)i*L_];
    g_s[idx] = acc;
}

// ---------------------------------------------------------------------------
// ks_sum[b,h,m] = sum_j s[h,j] * kp[b,h,j,m]      (one block per (b,h))
// ---------------------------------------------------------------------------
__global__ __launch_bounds__(128) void kssum_kernel()
{
    int bh = blockIdx.x;
    int h  = bh % H_;
    const float* kpr = g_kp + (size_t)bh*L_*M_;
    const float* sr  = g_s + h*L_;

    float a[8];
#pragma unroll
    for (int m = 0; m < 8; m++) a[m] = 0.f;

    for (int j = threadIdx.x; j < L_; j += 128) {
        float sv = sr[j];
        float4 x = ((const float4*)(kpr + j*8))[0];
        float4 y = ((const float4*)(kpr + j*8))[1];
        a[0] += sv*x.x; a[1] += sv*x.y; a[2] += sv*x.z; a[3] += sv*x.w;
        a[4] += sv*y.x; a[5] += sv*y.y; a[6] += sv*y.z; a[7] += sv*y.w;
    }
#pragma unroll
    for (int off = 16; off > 0; off >>= 1) {
#pragma unroll
        for (int m = 0; m < 8; m++)
            a[m] += __shfl_down_sync(0xffffffffu, a[m], off);
    }
    __shared__ float red[4][8];
    int w = threadIdx.x >> 5, lane = threadIdx.x & 31;
    if (lane == 0) {
#pragma unroll
        for (int m = 0; m < 8; m++) red[w][m] = a[m];
    }
    __syncthreads();
    if (threadIdx.x < 8) {
        g_ks[bh*8 + threadIdx.x] = red[0][threadIdx.x] + red[1][threadIdx.x]
                                 + red[2][threadIdx.x] + red[3][threadIdx.x];
    }
}

// ---------------------------------------------------------------------------
// Main kernel: per (b,h), tile I=64 rows of i; loop j in tiles of 64.
//   W[i,jj] = mask[h,i,j] * dot8(qp[i], kp[j])      (staged in smem)
//   acc[i,d] += W[i,jj] * v[b,j,h,d]                (8i x 8d regs, f32x2 FMA)
// Epilogue divides by normalizer = qp[i] . ks_sum[b,h].
// ---------------------------------------------------------------------------
__global__ __launch_bounds__(64) void attn_kernel(const float* __restrict__ v,
                                                  const float* __restrict__ mask,
                                                  float* __restrict__ out)
{
    const int i0 = blockIdx.x * 64;
    const int h  = blockIdx.y;
    const int b  = blockIdx.z;
    const int bh = b*H_ + h;
    const int t  = threadIdx.x;   // 0..63
    const int tx = t & 7;         // d-quad group: d = tx*4..+3 and 32+tx*4..+3
    const int ty = t >> 3;        // i-group: rows ty*4..+3 and 32+ty*4..+3

    __shared__ float qp_s[64*8];
    __shared__ float v_s [64*64];
    __shared__ float w_s [64*65];   // [jj][i], padded row 65 -> conflict-free STS

    // qp tile for this block (row t)
    {
        const float4* src = (const float4*)(g_qp + ((size_t)bh*L_ + i0 + t)*8);
        ((float4*)qp_s)[t*2]     = src[0];
        ((float4*)qp_s)[t*2 + 1] = src[1];
    }

    unsigned long long acc[8][4];
#pragma unroll
    for (int r = 0; r < 8; r++)
#pragma unroll
        for (int c = 0; c < 4; c++) acc[r][c] = 0ull;

    const float* vb  = v + ((size_t)b*L_*H_ + h)*64;          // + j*H*64 + d
    const float* mb  = mask + (size_t)h*L_*L_ + (size_t)i0*L_;
    const float* kpb = g_kp + (size_t)bh*L_*8;

    for (int j0 = 0; j0 < L_; j0 += 64) {
        __syncthreads();   // previous main loop done before smem reuse

        // stage v tile [jj][d]: 64 rows x 64 floats, coalesced
#pragma unroll
        for (int qq = 0; qq < 16; qq++) {
            int idx = qq*64 + t;
            int jj = idx >> 4, c = idx & 15;
            *(float4*)(v_s + jj*64 + c*4) =
                *(const float4*)(vb + (size_t)(j0 + jj)*(H_*64) + c*4);
        }

        // this thread's k' row (jj = t), kept in registers for W phase
        float kpv[8];
        {
            float4 a  = ((const float4*)(kpb + (size_t)(j0 + t)*8))[0];
            float4 bb = ((const float4*)(kpb + (size_t)(j0 + t)*8))[1];
            kpv[0]=a.x; kpv[1]=a.y; kpv[2]=a.z; kpv[3]=a.w;
            kpv[4]=bb.x; kpv[5]=bb.y; kpv[6]=bb.z; kpv[7]=bb.w;
        }

        // W phase: iterate i rows; lanes cover jj (mask loads coalesced)
#pragma unroll 4
        for (int kI = 0; kI < 64; kI++) {
            float4 qa = *(const float4*)(qp_s + kI*8);
            float4 qb = *(const float4*)(qp_s + kI*8 + 4);
            float  mval = mb[(size_t)kI*L_ + j0 + t];
            float  dot = qa.x*kpv[0] + qa.y*kpv[1] + qa.z*kpv[2] + qa.w*kpv[3]
                       + qb.x*kpv[4] + qb.y*kpv[5] + qb.z*kpv[6] + qb.w*kpv[7];
            w_s[t*65 + kI] = mval * dot;   // banks (t + kI) % 32: conflict-free
        }
        __syncthreads();

        // main accumulation: 8i x 8d per thread with packed f32x2 FMA
#pragma unroll 8
        for (int jj = 0; jj < 64; jj++) {
            ulonglong2 v01 = *(const ulonglong2*)(v_s + jj*64 + tx*4);
            ulonglong2 v23 = *(const ulonglong2*)(v_s + jj*64 + 32 + tx*4);
#pragma unroll
            for (int r = 0; r < 8; r++) {
                int row = (r < 4) ? (ty*4 + r) : (32 + ty*4 + r - 4);
                float w = w_s[jj*65 + row];
                unsigned long long wd;
                asm("mov.b64 %0, {%1, %1};" : "=l"(wd) : "f"(w));
                asm("fma.rn.f32x2 %0, %1, %2, %0;" : "+l"(acc[r][0]) : "l"(wd), "l"(v01.x));
                asm("fma.rn.f32x2 %0, %1, %2, %0;" : "+l"(acc[r][1]) : "l"(wd), "l"(v01.y));
                asm("fma.rn.f32x2 %0, %1, %2, %0;" : "+l"(acc[r][2]) : "l"(wd), "l"(v23.x));
                asm("fma.rn.f32x2 %0, %1, %2, %0;" : "+l"(acc[r][3]) : "l"(wd), "l"(v23.y));
            }
        }
    }

    // epilogue: normalizer + store
    float ks[8];
    {
        float4 a  = ((const float4*)(g_ks + bh*8))[0];
        float4 bb = ((const float4*)(g_ks + bh*8))[1];
        ks[0]=a.x; ks[1]=a.y; ks[2]=a.z; ks[3]=a.w;
        ks[4]=bb.x; ks[5]=bb.y; ks[6]=bb.z; ks[7]=bb.w;
    }
#pragma unroll
    for (int r = 0; r < 8; r++) {
        int row = (r < 4) ? (ty*4 + r) : (32 + ty*4 + r - 4);
        float n = 0.f;
#pragma unroll
        for (int m = 0; m < 8; m++) n += qp_s[row*8 + m] * ks[m];
        float inv = 1.0f / n;

        float o[8];
#pragma unroll
        for (int c = 0; c < 4; c++)
            asm("mov.b64 {%0, %1}, %2;" : "=f"(o[2*c]), "=f"(o[2*c+1]) : "l"(acc[r][c]));

        float* op = out + (((size_t)b*L_ + i0 + row)*H_ + h)*64;
        float4 lo = make_float4(o[0]*inv, o[1]*inv, o[2]*inv, o[3]*inv);
        float4 hi = make_float4(o[4]*inv, o[5]*inv, o[6]*inv, o[7]*inv);
        *(float4*)(op + tx*4)      = lo;
        *(float4*)(op + 32 + tx*4) = hi;
    }
}

// ---------------------------------------------------------------------------
extern "C" void kernel_launch(void* const* d_in, const int* in_sizes, int n_in,
                              void* d_out, int out_size)
{
    const float* q    = (const float*)d_in[0];
    const float* k    = (const float*)d_in[1];
    const float* v    = (const float*)d_in[2];
    const float* proj = (const float*)d_in[3];
    const float* mask = (const float*)d_in[4];
    float* out = (float*)d_out;

    dim3 fg((B_*L_*H_ + 127)/128, 2);
    feat_kernel<<<fg, 128>>>(q, k, proj);
    colsum_kernel<<<(H_*L_ + 255)/256, 256>>>(mask);
    kssum_kernel<<<B_*H_, 128>>>();
    attn_kernel<<<dim3(L_/64, H_, B_), 64>>>(v, mask, out);
}